// round 11
// baseline (speedup 1.0000x reference)
#include <cuda_runtime.h>
#include <math.h>
#include <stdint.h>

#define Bsz 32
#define Nn  500
#define Gg  500
#define Hh  128
#define KNB 16

// ---------------- scratch (device globals; no allocation) ----------------
__device__ float g_colsum[Bsz*Hh];
__device__ float g_Wall[Hh*384];             // [k][j]: j<128 Wk^T, <256 Wv^T, <384 Wc
__device__ float g_WqT[Hh*Hh];               // [k][o] = Wq_first[o][k]+Wq_last[o][k]
__device__ float g_embT[Bsz*Hh*Nn];          // (B,128,N)  k-major embeddings
__device__ float g_lastT[Bsz*Hh*Gg];         // (B,128,G)  k-major gathered last_emb
__device__ float g_K[(size_t)Bsz*Nn*Hh];     // (B,N,128)
__device__ float g_V[(size_t)Bsz*Nn*Hh];     // (B,N,128)
__device__ float g_EpT[Bsz*Hh*Nn];           // (B,128,N)  E' = emb@Wc, k-major
__device__ float g_biasE[Bsz*Nn];            // bc . emb[b,n]
__device__ float g_Q[(size_t)Bsz*Gg*Hh];     // (B,G,128)
__device__ float g_attnT[Bsz*Hh*Gg];         // (B,128,G)  attention out, k-major

// ---------------- f32x2 packed-FMA fabric ----------------
__device__ __forceinline__ void ffma2(unsigned long long &d, unsigned long long a, unsigned long long b) {
    asm("fma.rn.f32x2 %0, %1, %2, %0;" : "+l"(d) : "l"(a), "l"(b));
}
__device__ __forceinline__ unsigned long long bpack(float x) {
    unsigned long long r;
    asm("mov.b64 %0, {%1, %1};" : "=l"(r) : "f"(x));
    return r;
}
__device__ __forceinline__ void unpack2(unsigned long long v, float &lo, float &hi) {
    asm("mov.b64 {%0, %1}, %2;" : "=f"(lo), "=f"(hi) : "l"(v));
}

// 64-k chunk of the 8x8 micro-tile mainloop. As/Bs: [64][128].
__device__ __forceinline__ void mm64(const float* __restrict__ As, const float* __restrict__ Bs,
                                     int ty, int tx, unsigned long long acc[4][8]) {
#pragma unroll 8
    for (int k = 0; k < 64; ++k) {
        ulonglong2 aA = *(const ulonglong2*)(As + k*128 + ty*8);
        ulonglong2 aB = *(const ulonglong2*)(As + k*128 + ty*8 + 4);
        float4 b0 = *(const float4*)(Bs + k*128 + tx*8);
        float4 b1 = *(const float4*)(Bs + k*128 + tx*8 + 4);
        unsigned long long bb[8];
        bb[0]=bpack(b0.x); bb[1]=bpack(b0.y); bb[2]=bpack(b0.z); bb[3]=bpack(b0.w);
        bb[4]=bpack(b1.x); bb[5]=bpack(b1.y); bb[6]=bpack(b1.z); bb[7]=bpack(b1.w);
#pragma unroll
        for (int c = 0; c < 8; ++c) {
            ffma2(acc[0][c], aA.x, bb[c]);
            ffma2(acc[1][c], aA.y, bb[c]);
            ffma2(acc[2][c], aB.x, bb[c]);
            ffma2(acc[3][c], aB.y, bb[c]);
        }
    }
}
__device__ __forceinline__ void unpack_acc(unsigned long long acc[4][8], float accf[8][8]) {
#pragma unroll
    for (int rp = 0; rp < 4; ++rp)
#pragma unroll
        for (int c = 0; c < 8; ++c)
            unpack2(acc[rp][c], accf[2*rp][c], accf[2*rp+1][c]);
}

// fill one [64][128] k-chunk from k-major src (row pitch), cols j0.., guard jmax
__device__ __forceinline__ void fill_k(float* __restrict__ dst, const float* __restrict__ src,
                                       int pitch, int j0, int jmax, int kc, int tid) {
#pragma unroll
    for (int it = 0; it < 8; ++it) {
        int idx = tid + it*256;          // 2048 float4 slots
        int k = idx >> 5, jq = idx & 31;
        int j = j0 + jq*4;
        const float* p = src + (size_t)(kc*64 + k)*pitch + j;
        float4 v;
        if (j + 3 < jmax) v = *(const float4*)p;
        else {
            v.x = (j   < jmax) ? p[0] : 0.f;
            v.y = (j+1 < jmax) ? p[1] : 0.f;
            v.z = (j+2 < jmax) ? p[2] : 0.f;
            v.w = (j+3 < jmax) ? p[3] : 0.f;
        }
        *(float4*)(dst + k*128 + jq*4) = v;
    }
}

// fast tanh: (1 - e) * rcp(1 + e), e = exp(-2|x|); err ~1e-7
__device__ __forceinline__ float fast_tanh(float x) {
    float a = fabsf(x);
    float e = __expf(-2.f * a);
    float t = __fdividef(1.f - e, 1.f + e);
    return copysignf(t, x);
}

// ---------------- prep1: weight transposes + zero colsum/biasE ----------------
__global__ void prep1_kernel(const float* __restrict__ Wk, const float* __restrict__ Wv,
                             const float* __restrict__ Wc, const float* __restrict__ Wqf,
                             const float* __restrict__ Wql) {
    int idx = blockIdx.x * blockDim.x + threadIdx.x;
    const int total1 = Hh * 384;
    if (idx < total1) {
        int k = idx / 384, j = idx % 384;
        float v;
        if (j < 128)      v = Wk[j*128 + k];
        else if (j < 256) v = Wv[(j-128)*128 + k];
        else              v = Wc[k*128 + (j-256)];
        g_Wall[idx] = v;
    }
    int idx2 = idx - total1;
    if (idx2 >= 0 && idx2 < Hh*Hh) {
        int k = idx2 / 128, o = idx2 % 128;
        g_WqT[idx2] = Wqf[o*128 + k] + Wql[o*128 + k];
    }
    if (idx < Bsz*Hh) g_colsum[idx] = 0.f;
    if (idx < Bsz*Nn) g_biasE[idx] = 0.f;
}

// ---------------- prep2: embT(+colsum+biasE) and lastT, merged ----------------
__global__ void prep2_kernel(const float* __restrict__ emb, const float* __restrict__ bc,
                             const int* __restrict__ last) {
    __shared__ float tile[32][33];
    int tid = threadIdx.x;
    int tx = tid & 31, ty = tid >> 5;
    int bid = blockIdx.x;
    if (bid < 2048) {
        int b = bid >> 6, k0 = ((bid >> 4) & 3) * 32, n0 = (bid & 15) * 32;
        float bcv = bc[k0 + tx];
        float csum = 0.f;
#pragma unroll
        for (int i = 0; i < 32; i += 8) {
            int n = n0 + ty + i;
            float v = 0.f;
            if (n < Nn) { v = emb[((size_t)b*Nn + n)*Hh + k0 + tx]; tile[ty+i][tx] = v; }
            csum += v;
            float contrib = v * bcv;
            for (int off = 16; off; off >>= 1)
                contrib += __shfl_xor_sync(0xffffffffu, contrib, off);
            if (tx == 0 && n < Nn) atomicAdd(&g_biasE[b*Nn + n], contrib);
        }
        atomicAdd(&g_colsum[b*128 + k0 + tx], csum);
        __syncthreads();
#pragma unroll
        for (int i = 0; i < 32; i += 8) {
            int k = k0 + ty + i, n = n0 + tx;
            if (n < Nn) g_embT[(size_t)b*Hh*Nn + k*Nn + n] = tile[tx][ty+i];
        }
    } else {
        int e = bid - 2048;
        int b = e >> 6, k0 = ((e >> 4) & 3) * 32, g0 = (e & 15) * 32;
#pragma unroll
        for (int i = 0; i < 32; i += 8) {
            int g = g0 + ty + i;
            if (g < Gg) {
                int row = last[b*Gg + g];
                tile[ty+i][tx] = emb[((size_t)b*Nn + row)*Hh + k0 + tx];
            }
        }
        __syncthreads();
#pragma unroll
        for (int i = 0; i < 32; i += 8) {
            int k = k0 + ty + i, g = g0 + tx;
            if (g < Gg) g_lastT[(size_t)b*Hh*Gg + k*Gg + g] = tile[tx][ty+i];
        }
    }
}

// ---------------- gemms: A-path (K|V|E') and Q-path (+q_graph), merged ----------------
__global__ __launch_bounds__(256, 2) void gemms_kernel(const float* __restrict__ Wqg) {
    extern __shared__ float sm[];
    float* As = sm;
    float* Bs = sm + 8192;
    __shared__ float mean_s[128];
    __shared__ float qg_s[128];
    int tid = threadIdx.x;
    int bid = blockIdx.x;
    int ty = tid >> 4, tx = tid & 15;
    unsigned long long acc[4][8];
#pragma unroll
    for (int rp = 0; rp < 4; ++rp)
#pragma unroll
        for (int c = 0; c < 8; ++c) acc[rp][c] = 0ull;

    if (bid < 384) {
        int c = bid % 3, nt = (bid / 3) % 4, b = bid / 12;
        int c0 = c * 128, n0 = nt * 128;
        const float* embTb = g_embT + (size_t)b*Hh*Nn;
#pragma unroll
        for (int kc = 0; kc < 2; ++kc) {
            fill_k(As, embTb, Nn, n0, Nn, kc, tid);
            fill_k(Bs, g_Wall, 384, c0, 1 << 30, kc, tid);
            __syncthreads();
            mm64(As, Bs, ty, tx, acc);
            __syncthreads();
        }
        float accf[8][8];
        unpack_acc(acc, accf);
        if (c0 < 256) {
            float* dst = (c0 == 0) ? g_K : g_V;
#pragma unroll
            for (int p = 0; p < 8; ++p) {
                int r = n0 + ty*8 + p;
                if (r >= Nn) continue;
                float* o = dst + ((size_t)b*Nn + r)*Hh + tx*8;
                *(float4*)o       = make_float4(accf[p][0], accf[p][1], accf[p][2], accf[p][3]);
                *(float4*)(o + 4) = make_float4(accf[p][4], accf[p][5], accf[p][6], accf[p][7]);
            }
        } else {
            float* st = sm;  // [128][129]
#pragma unroll
            for (int q = 0; q < 8; ++q)
#pragma unroll
                for (int p = 0; p < 8; ++p)
                    st[(tx*8 + q)*129 + ty*8 + p] = accf[p][q];
            __syncthreads();
            float* EpTb = g_EpT + (size_t)b*Hh*Nn;
            for (int s = tid; s < 16384; s += 256) {
                int cc = s >> 7, n = s & 127;
                if (n0 + n < Nn) EpTb[(size_t)cc*Nn + n0 + n] = st[cc*129 + n];
            }
        }
    } else {
        int q = bid - 384;
        int gt = q % 4, b = q / 4;
        int g0 = gt * 128;
        if (tid < 128) mean_s[tid] = g_colsum[b*128 + tid] * (1.f / (float)Nn);
        __syncthreads();
        {
            int w = tid >> 5, lane = tid & 31;
            for (int o = w*16; o < w*16 + 16; ++o) {
                float s = 0.f;
#pragma unroll
                for (int i = lane; i < 128; i += 32) s += mean_s[i] * Wqg[o*128 + i];
                for (int off = 16; off; off >>= 1) s += __shfl_xor_sync(0xffffffffu, s, off);
                if (lane == 0) qg_s[o] = s;
            }
        }
        const float* lastTb = g_lastT + (size_t)b*Hh*Gg;
#pragma unroll
        for (int kc = 0; kc < 2; ++kc) {
            fill_k(As, lastTb, Gg, g0, Gg, kc, tid);
            fill_k(Bs, g_WqT, 128, 0, 1 << 30, kc, tid);
            __syncthreads();
            mm64(As, Bs, ty, tx, acc);
            __syncthreads();
        }
        float accf[8][8];
        unpack_acc(acc, accf);
        float4 qg0 = *(const float4*)(qg_s + tx*8);
        float4 qg1 = *(const float4*)(qg_s + tx*8 + 4);
#pragma unroll
        for (int p = 0; p < 8; ++p) {
            int r = g0 + ty*8 + p;
            if (r >= Gg) continue;
            float* o = g_Q + ((size_t)b*Gg + r)*Hh + tx*8;
            *(float4*)o       = make_float4(accf[p][0]+qg0.x, accf[p][1]+qg0.y, accf[p][2]+qg0.z, accf[p][3]+qg0.w);
            *(float4*)(o + 4) = make_float4(accf[p][4]+qg1.x, accf[p][5]+qg1.y, accf[p][6]+qg1.z, accf[p][7]+qg1.w);
        }
    }
}

// ---------------- glimpse: histogram top-16 (exact) + head-parallel attention ----------------
__global__ __launch_bounds__(128) void glimpse_kernel(const float* __restrict__ coords,
                                                      const float* __restrict__ mask,
                                                      const int* __restrict__ last) {
    __shared__ uint32_t hist[256];
    __shared__ int   sel[KNB];
    __shared__ unsigned long long cand[Nn];
    __shared__ __align__(16) float qsh[128];
    __shared__ __align__(16) float vsh[KNB*128];
    __shared__ float wsh[128];
    __shared__ int cnt1, cnt2, sT;
    int g = blockIdx.x, b = blockIdx.y;
    int tid = threadIdx.x;

    hist[tid] = 0u; hist[tid + 128] = 0u;
    if (tid == 0) { cnt1 = 0; cnt2 = 0; }
    qsh[tid] = g_Q[((size_t)b*Gg + g)*Hh + tid];

    int idxLast = last[b*Gg + g];
    const float2* cb = (const float2*)coords + (size_t)b*Nn;
    float2 lc = cb[idxLast];
    __syncthreads();

    // build keys + histogram on floor(d2*128)  (order-consistent with sqrt key)
    unsigned long long key[4];
    int bkt[4];
    const float* mrow = mask + ((size_t)b*Gg + g)*Nn;
#pragma unroll
    for (int i = 0; i < 4; ++i) {
        int n = tid + 128*i;
        key[i] = ~0ull; bkt[i] = -1;
        if (n < Nn) {
            float m = mrow[n];
            if (m == -INFINITY) {
                key[i] = (0x7F800000ull << 32) | (unsigned)n;
                bkt[i] = 255;
            } else {
                float2 c = cb[n];
                float dx = lc.x - c.x, dy = lc.y - c.y;
                float d2 = dx*dx + dy*dy;
                float d = sqrtf(d2);
                key[i] = ((unsigned long long)__float_as_uint(d) << 32) | (unsigned)n;
                bkt[i] = min(255, (int)(d2 * 128.0f));
            }
            atomicAdd(&hist[bkt[i]], 1u);
        }
    }
    __syncthreads();

    // warp 0: scan 256 buckets, find T = first bucket with cum >= 16
    if (tid < 32) {
        int base = tid * 8;
        uint32_t h[8], s = 0;
#pragma unroll
        for (int k = 0; k < 8; ++k) { h[k] = hist[base + k]; s += h[k]; }
        uint32_t c = s;
#pragma unroll
        for (int off = 1; off < 32; off <<= 1) {
            uint32_t o = __shfl_up_sync(0xffffffffu, c, off);
            if (tid >= off) c += o;
        }
        uint32_t bal = __ballot_sync(0xffffffffu, c >= KNB);
        int L = __ffs(bal) - 1;
        if (tid == L) {
            uint32_t run = c - s;
            int T = base;
#pragma unroll
            for (int k = 0; k < 8; ++k) {
                if (run + h[k] >= KNB) { T = base + k; break; }
                run += h[k];
            }
            sT = T;
        }
    }
    __syncthreads();
    int T = sT;

    // classify: bucket<T auto-selected; bucket==T gathered for exact refinement
#pragma unroll
    for (int i = 0; i < 4; ++i) {
        if (bkt[i] >= 0) {
            if (bkt[i] < T)       { int p = atomicAdd(&cnt1, 1); sel[p] = (int)(key[i] & 0xffffffffu); }
            else if (bkt[i] == T) { int p = atomicAdd(&cnt2, 1); cand[p] = key[i]; }
        }
    }
    __syncthreads();

    if (tid == 0) {
        int c1 = cnt1, m2 = cnt2;
        int need = KNB - c1;
        for (int it = 0; it < need; ++it) {
            unsigned long long best = ~0ull; int bi = 0;
            for (int k = 0; k < m2; ++k)
                if (cand[k] < best) { best = cand[k]; bi = k; }
            cand[bi] = ~0ull;
            sel[c1 + it] = (int)(best & 0xffffffffu);
        }
    }
    __syncthreads();

    // attention: thread (h,j) does full 16-dim dot for head h, neighbor j
    int h = tid >> 4, j = tid & 15;
    {
        int n = sel[j];
        const float* Krow = g_K + ((size_t)b*Nn + n)*Hh + h*16;
        const float* Vrow = g_V + ((size_t)b*Nn + n)*Hh + h*16;
        float4 q0 = *(const float4*)(qsh + h*16);
        float4 q1 = *(const float4*)(qsh + h*16 + 4);
        float4 q2 = *(const float4*)(qsh + h*16 + 8);
        float4 q3 = *(const float4*)(qsh + h*16 + 12);
        float4 kk0 = *(const float4*)(Krow);
        float4 kk1 = *(const float4*)(Krow + 4);
        float4 kk2 = *(const float4*)(Krow + 8);
        float4 kk3 = *(const float4*)(Krow + 12);
        float p = q0.x*kk0.x + q0.y*kk0.y + q0.z*kk0.z + q0.w*kk0.w
                + q1.x*kk1.x + q1.y*kk1.y + q1.z*kk1.z + q1.w*kk1.w
                + q2.x*kk2.x + q2.y*kk2.y + q2.z*kk2.z + q2.w*kk2.w
                + q3.x*kk3.x + q3.y*kk3.y + q3.z*kk3.z + q3.w*kk3.w;
        p *= 0.25f;   // 1/sqrt(16)
        // stage V head-slice to smem
        *(float4*)(vsh + j*128 + h*16)      = *(const float4*)(Vrow);
        *(float4*)(vsh + j*128 + h*16 + 4)  = *(const float4*)(Vrow + 4);
        *(float4*)(vsh + j*128 + h*16 + 8)  = *(const float4*)(Vrow + 8);
        *(float4*)(vsh + j*128 + h*16 + 12) = *(const float4*)(Vrow + 12);
        // softmax over j (width-16 segments align with heads)
        float mx = p;
#pragma unroll
        for (int off = 8; off; off >>= 1) mx = fmaxf(mx, __shfl_xor_sync(0xffffffffu, mx, off, 16));
        float e = __expf(p - mx);
        float s = e;
#pragma unroll
        for (int off = 8; off; off >>= 1) s += __shfl_xor_sync(0xffffffffu, s, off, 16);
        wsh[tid] = e * (1.f / s);
    }
    __syncthreads();

    // output: thread (h,d) combines 16 neighbors
    float o = 0.f;
#pragma unroll
    for (int j2 = 0; j2 < KNB; ++j2) o += wsh[h*16 + j2] * vsh[j2*128 + tid];
    g_attnT[(size_t)b*Hh*Gg + tid*Gg + g] = o;
}

// ---------------- F1: pointer GEMM + tanh + mask -> scores in out ----------------
__global__ __launch_bounds__(256, 2) void final_gemm_kernel(const float* __restrict__ mask,
                                                            float* __restrict__ out) {
    extern __shared__ float sm[];
    float* As = sm;
    float* Bs = sm + 8192;
    int b = blockIdx.z, n0 = blockIdx.x * 128, g0 = blockIdx.y * 128;
    int tid = threadIdx.x;
    int ty = tid >> 4, tx = tid & 15;
    unsigned long long acc[4][8];
#pragma unroll
    for (int rp = 0; rp < 4; ++rp)
#pragma unroll
        for (int c = 0; c < 8; ++c) acc[rp][c] = 0ull;

    const float* attnTb = g_attnT + (size_t)b*Hh*Gg;
    const float* EpTb   = g_EpT   + (size_t)b*Hh*Nn;
#pragma unroll
    for (int kc = 0; kc < 2; ++kc) {
        fill_k(As, attnTb, Gg, g0, Gg, kc, tid);
        fill_k(Bs, EpTb,   Nn, n0, Nn, kc, tid);
        __syncthreads();
        mm64(As, Bs, ty, tx, acc);
        __syncthreads();
    }
    float accf[8][8];
    unpack_acc(acc, accf);

    float be[8];
#pragma unroll
    for (int q = 0; q < 8; ++q) {
        int n = n0 + tx*8 + q;
        be[q] = (n < Nn) ? g_biasE[b*Nn + n] : 0.f;
    }
#pragma unroll
    for (int p = 0; p < 8; ++p) {
        int g = g0 + ty*8 + p;
        if (g >= Gg) continue;
        const float* mrow = mask + ((size_t)b*Gg + g)*Nn;
        float* orow = out + ((size_t)b*Gg + g)*Nn;
#pragma unroll
        for (int q = 0; q < 8; ++q) {
            int n = n0 + tx*8 + q;
            if (n >= Nn) continue;
            float s = accf[p][q] + be[q];
            orow[n] = fast_tanh(s) * 10.0f + mrow[n];
        }
    }
}

// ---------------- F2: warp-per-row softmax, in place on out ----------------
__global__ __launch_bounds__(256) void softmax_kernel(float* __restrict__ out) {
    int warp = threadIdx.x >> 5, lane = threadIdx.x & 31;
    int r = blockIdx.x * 8 + warp;
    if (r >= Bsz*Gg) return;
    float* row = out + (size_t)r*Nn;
    float v[16];
    float m = -INFINITY;
#pragma unroll
    for (int i = 0; i < 16; ++i) {
        int n = lane + i*32;
        v[i] = (n < Nn) ? row[n] : -INFINITY;
        m = fmaxf(m, v[i]);
    }
    for (int off = 16; off; off >>= 1) m = fmaxf(m, __shfl_xor_sync(0xffffffffu, m, off));
    float s = 0.f;
#pragma unroll
    for (int i = 0; i < 16; ++i) { float e = __expf(v[i] - m); v[i] = e; s += e; }
    for (int off = 16; off; off >>= 1) s += __shfl_xor_sync(0xffffffffu, s, off);
    float inv = 1.f / s;
#pragma unroll
    for (int i = 0; i < 16; ++i) {
        int n = lane + i*32;
        if (n < Nn) row[n] = v[i] * inv;
    }
}

// ---------------- host ----------------
extern "C" void kernel_launch(void* const* d_in, const int* in_sizes, int n_in,
                              void* d_out, int out_size) {
    const float* coords   = (const float*)d_in[0];
    const float* emb      = (const float*)d_in[1];
    const int*   last     = (const int*)  d_in[2];
    const float* mask     = (const float*)d_in[3];
    const float* Wq_graph = (const float*)d_in[4];
    const float* Wq_first = (const float*)d_in[5];
    const float* Wq_last  = (const float*)d_in[6];
    const float* Wk       = (const float*)d_in[7];
    const float* Wv       = (const float*)d_in[8];
    const float* Wc       = (const float*)d_in[9];
    const float* bc       = (const float*)d_in[10];
    float* out = (float*)d_out;

    cudaFuncSetAttribute(gemms_kernel,      cudaFuncAttributeMaxDynamicSharedMemorySize, 66048);
    cudaFuncSetAttribute(final_gemm_kernel, cudaFuncAttributeMaxDynamicSharedMemorySize, 65536);

    prep1_kernel<<<256, 256>>>(Wk, Wv, Wc, Wq_first, Wq_last);
    prep2_kernel<<<4096, 256>>>(emb, bc, last);
    gemms_kernel<<<512, 256, 66048>>>(Wq_graph);
    glimpse_kernel<<<dim3(Gg, Bsz), 128>>>(coords, mask, last);
    final_gemm_kernel<<<dim3(4, 4, Bsz), 256, 65536>>>(mask, out);
    softmax_kernel<<<2000, 256>>>(out);
}

// round 12
// speedup vs baseline: 1.0128x; 1.0128x over previous
#include <cuda_runtime.h>
#include <math.h>
#include <stdint.h>

#define Bsz 32
#define Nn  500
#define Gg  500
#define Hh  128
#define KNB 16

// ---------------- scratch (device globals; no allocation) ----------------
__device__ float g_colsum[Bsz*Hh];
__device__ float g_Wall[Hh*384];             // [k][j]: j<128 Wk^T, <256 Wv^T, <384 Wc
__device__ float g_WqT[Hh*Hh];               // [k][o] = Wq_first[o][k]+Wq_last[o][k]
__device__ float g_embT[Bsz*Hh*Nn];          // (B,128,N)  k-major embeddings
__device__ float g_lastT[Bsz*Hh*Gg];         // (B,128,G)  k-major gathered last_emb
__device__ float g_K[(size_t)Bsz*Nn*Hh];     // (B,N,128)
__device__ float g_V[(size_t)Bsz*Nn*Hh];     // (B,N,128)
__device__ float g_EpT[Bsz*Hh*Nn];           // (B,128,N)  E' = emb@Wc, k-major
__device__ float g_biasE[Bsz*Nn];            // bc . emb[b,n]
__device__ float g_Q[(size_t)Bsz*Gg*Hh];     // (B,G,128)
__device__ float g_attnT[Bsz*Hh*Gg];         // (B,128,G)  attention out, k-major

// ---------------- f32x2 packed-FMA fabric ----------------
__device__ __forceinline__ void ffma2(unsigned long long &d, unsigned long long a, unsigned long long b) {
    asm("fma.rn.f32x2 %0, %1, %2, %0;" : "+l"(d) : "l"(a), "l"(b));
}
__device__ __forceinline__ unsigned long long bpack(float x) {
    unsigned long long r;
    asm("mov.b64 %0, {%1, %1};" : "=l"(r) : "f"(x));
    return r;
}
__device__ __forceinline__ void unpack2(unsigned long long v, float &lo, float &hi) {
    asm("mov.b64 {%0, %1}, %2;" : "=f"(lo), "=f"(hi) : "l"(v));
}

// 64-k chunk of the 8x8 micro-tile mainloop. As/Bs: [64][128].
__device__ __forceinline__ void mm64(const float* __restrict__ As, const float* __restrict__ Bs,
                                     int ty, int tx, unsigned long long acc[4][8]) {
#pragma unroll 8
    for (int k = 0; k < 64; ++k) {
        ulonglong2 aA = *(const ulonglong2*)(As + k*128 + ty*8);
        ulonglong2 aB = *(const ulonglong2*)(As + k*128 + ty*8 + 4);
        float4 b0 = *(const float4*)(Bs + k*128 + tx*8);
        float4 b1 = *(const float4*)(Bs + k*128 + tx*8 + 4);
        unsigned long long bb[8];
        bb[0]=bpack(b0.x); bb[1]=bpack(b0.y); bb[2]=bpack(b0.z); bb[3]=bpack(b0.w);
        bb[4]=bpack(b1.x); bb[5]=bpack(b1.y); bb[6]=bpack(b1.z); bb[7]=bpack(b1.w);
#pragma unroll
        for (int c = 0; c < 8; ++c) {
            ffma2(acc[0][c], aA.x, bb[c]);
            ffma2(acc[1][c], aA.y, bb[c]);
            ffma2(acc[2][c], aB.x, bb[c]);
            ffma2(acc[3][c], aB.y, bb[c]);
        }
    }
}
__device__ __forceinline__ void unpack_acc(unsigned long long acc[4][8], float accf[8][8]) {
#pragma unroll
    for (int rp = 0; rp < 4; ++rp)
#pragma unroll
        for (int c = 0; c < 8; ++c)
            unpack2(acc[rp][c], accf[2*rp][c], accf[2*rp+1][c]);
}

// fill one [64][128] k-chunk from k-major src (row pitch), cols j0.., guard jmax
__device__ __forceinline__ void fill_k(float* __restrict__ dst, const float* __restrict__ src,
                                       int pitch, int j0, int jmax, int kc, int tid) {
#pragma unroll
    for (int it = 0; it < 8; ++it) {
        int idx = tid + it*256;          // 2048 float4 slots
        int k = idx >> 5, jq = idx & 31;
        int j = j0 + jq*4;
        const float* p = src + (size_t)(kc*64 + k)*pitch + j;
        float4 v;
        if (j + 3 < jmax) v = *(const float4*)p;
        else {
            v.x = (j   < jmax) ? p[0] : 0.f;
            v.y = (j+1 < jmax) ? p[1] : 0.f;
            v.z = (j+2 < jmax) ? p[2] : 0.f;
            v.w = (j+3 < jmax) ? p[3] : 0.f;
        }
        *(float4*)(dst + k*128 + jq*4) = v;
    }
}

// fast tanh: (1 - e) * rcp(1 + e), e = exp(-2|x|); err ~1e-7
__device__ __forceinline__ float fast_tanh(float x) {
    float a = fabsf(x);
    float e = __expf(-2.f * a);
    float t = __fdividef(1.f - e, 1.f + e);
    return copysignf(t, x);
}

// ---------------- prep1: weight transposes + zero colsum/biasE ----------------
__global__ void prep1_kernel(const float* __restrict__ Wk, const float* __restrict__ Wv,
                             const float* __restrict__ Wc, const float* __restrict__ Wqf,
                             const float* __restrict__ Wql) {
    int idx = blockIdx.x * blockDim.x + threadIdx.x;
    const int total1 = Hh * 384;
    if (idx < total1) {
        int k = idx / 384, j = idx % 384;
        float v;
        if (j < 128)      v = Wk[j*128 + k];
        else if (j < 256) v = Wv[(j-128)*128 + k];
        else              v = Wc[k*128 + (j-256)];
        g_Wall[idx] = v;
    }
    int idx2 = idx - total1;
    if (idx2 >= 0 && idx2 < Hh*Hh) {
        int k = idx2 / 128, o = idx2 % 128;
        g_WqT[idx2] = Wqf[o*128 + k] + Wql[o*128 + k];
    }
    if (idx < Bsz*Hh) g_colsum[idx] = 0.f;
    if (idx < Bsz*Nn) g_biasE[idx] = 0.f;
}

// ---------------- prep2: embT(+colsum+biasE) and lastT, merged ----------------
__global__ void prep2_kernel(const float* __restrict__ emb, const float* __restrict__ bc,
                             const int* __restrict__ last) {
    __shared__ float tile[32][33];
    int tid = threadIdx.x;
    int tx = tid & 31, ty = tid >> 5;
    int bid = blockIdx.x;
    if (bid < 2048) {
        int b = bid >> 6, k0 = ((bid >> 4) & 3) * 32, n0 = (bid & 15) * 32;
        float bcv = bc[k0 + tx];
        float csum = 0.f;
#pragma unroll
        for (int i = 0; i < 32; i += 8) {
            int n = n0 + ty + i;
            float v = 0.f;
            if (n < Nn) { v = emb[((size_t)b*Nn + n)*Hh + k0 + tx]; tile[ty+i][tx] = v; }
            csum += v;
            float contrib = v * bcv;
            for (int off = 16; off; off >>= 1)
                contrib += __shfl_xor_sync(0xffffffffu, contrib, off);
            if (tx == 0 && n < Nn) atomicAdd(&g_biasE[b*Nn + n], contrib);
        }
        atomicAdd(&g_colsum[b*128 + k0 + tx], csum);
        __syncthreads();
#pragma unroll
        for (int i = 0; i < 32; i += 8) {
            int k = k0 + ty + i, n = n0 + tx;
            if (n < Nn) g_embT[(size_t)b*Hh*Nn + k*Nn + n] = tile[tx][ty+i];
        }
    } else {
        int e = bid - 2048;
        int b = e >> 6, k0 = ((e >> 4) & 3) * 32, g0 = (e & 15) * 32;
#pragma unroll
        for (int i = 0; i < 32; i += 8) {
            int g = g0 + ty + i;
            if (g < Gg) {
                int row = last[b*Gg + g];
                tile[ty+i][tx] = emb[((size_t)b*Nn + row)*Hh + k0 + tx];
            }
        }
        __syncthreads();
#pragma unroll
        for (int i = 0; i < 32; i += 8) {
            int k = k0 + ty + i, g = g0 + tx;
            if (g < Gg) g_lastT[(size_t)b*Hh*Gg + k*Gg + g] = tile[tx][ty+i];
        }
    }
}

// ---------------- gemms: A-path (K|V|E') and Q-path (+q_graph), merged ----------------
__global__ __launch_bounds__(256, 2) void gemms_kernel(const float* __restrict__ Wqg) {
    extern __shared__ float sm[];
    float* As = sm;
    float* Bs = sm + 8192;
    __shared__ float mean_s[128];
    __shared__ float qg_s[128];
    int tid = threadIdx.x;
    int bid = blockIdx.x;
    int ty = tid >> 4, tx = tid & 15;
    unsigned long long acc[4][8];
#pragma unroll
    for (int rp = 0; rp < 4; ++rp)
#pragma unroll
        for (int c = 0; c < 8; ++c) acc[rp][c] = 0ull;

    if (bid < 384) {
        int c = bid % 3, nt = (bid / 3) % 4, b = bid / 12;
        int c0 = c * 128, n0 = nt * 128;
        const float* embTb = g_embT + (size_t)b*Hh*Nn;
#pragma unroll
        for (int kc = 0; kc < 2; ++kc) {
            fill_k(As, embTb, Nn, n0, Nn, kc, tid);
            fill_k(Bs, g_Wall, 384, c0, 1 << 30, kc, tid);
            __syncthreads();
            mm64(As, Bs, ty, tx, acc);
            __syncthreads();
        }
        float accf[8][8];
        unpack_acc(acc, accf);
        if (c0 < 256) {
            float* dst = (c0 == 0) ? g_K : g_V;
#pragma unroll
            for (int p = 0; p < 8; ++p) {
                int r = n0 + ty*8 + p;
                if (r >= Nn) continue;
                float* o = dst + ((size_t)b*Nn + r)*Hh + tx*8;
                *(float4*)o       = make_float4(accf[p][0], accf[p][1], accf[p][2], accf[p][3]);
                *(float4*)(o + 4) = make_float4(accf[p][4], accf[p][5], accf[p][6], accf[p][7]);
            }
        } else {
            float* st = sm;  // [128][129]
#pragma unroll
            for (int q = 0; q < 8; ++q)
#pragma unroll
                for (int p = 0; p < 8; ++p)
                    st[(tx*8 + q)*129 + ty*8 + p] = accf[p][q];
            __syncthreads();
            float* EpTb = g_EpT + (size_t)b*Hh*Nn;
            for (int s = tid; s < 16384; s += 256) {
                int cc = s >> 7, n = s & 127;
                if (n0 + n < Nn) EpTb[(size_t)cc*Nn + n0 + n] = st[cc*129 + n];
            }
        }
    } else {
        int q = bid - 384;
        int gt = q % 4, b = q / 4;
        int g0 = gt * 128;
        if (tid < 128) mean_s[tid] = g_colsum[b*128 + tid] * (1.f / (float)Nn);
        __syncthreads();
        {
            int w = tid >> 5, lane = tid & 31;
            for (int o = w*16; o < w*16 + 16; ++o) {
                float s = 0.f;
#pragma unroll
                for (int i = lane; i < 128; i += 32) s += mean_s[i] * Wqg[o*128 + i];
                for (int off = 16; off; off >>= 1) s += __shfl_xor_sync(0xffffffffu, s, off);
                if (lane == 0) qg_s[o] = s;
            }
        }
        const float* lastTb = g_lastT + (size_t)b*Hh*Gg;
#pragma unroll
        for (int kc = 0; kc < 2; ++kc) {
            fill_k(As, lastTb, Gg, g0, Gg, kc, tid);
            fill_k(Bs, g_WqT, 128, 0, 1 << 30, kc, tid);
            __syncthreads();
            mm64(As, Bs, ty, tx, acc);
            __syncthreads();
        }
        float accf[8][8];
        unpack_acc(acc, accf);
        float4 qg0 = *(const float4*)(qg_s + tx*8);
        float4 qg1 = *(const float4*)(qg_s + tx*8 + 4);
#pragma unroll
        for (int p = 0; p < 8; ++p) {
            int r = g0 + ty*8 + p;
            if (r >= Gg) continue;
            float* o = g_Q + ((size_t)b*Gg + r)*Hh + tx*8;
            *(float4*)o       = make_float4(accf[p][0]+qg0.x, accf[p][1]+qg0.y, accf[p][2]+qg0.z, accf[p][3]+qg0.w);
            *(float4*)(o + 4) = make_float4(accf[p][4]+qg1.x, accf[p][5]+qg1.y, accf[p][6]+qg1.z, accf[p][7]+qg1.w);
        }
    }
}

// ---------------- glimpse: warp-local top-16 (R9) + head-parallel attention ----------------
__device__ __forceinline__ void cswap(unsigned long long &a, unsigned long long &b) {
    unsigned long long lo = min(a, b), hi = max(a, b);
    a = lo; b = hi;
}

__global__ __launch_bounds__(128) void glimpse_kernel(const float* __restrict__ coords,
                                                      const float* __restrict__ mask,
                                                      const int* __restrict__ last) {
    __shared__ unsigned long long warp16[4][16];
    __shared__ int   sel[KNB];
    __shared__ __align__(16) float qsh[128];
    __shared__ __align__(16) float vsh[KNB*132];   // stride 132: avoid 16-way bank conflicts
    __shared__ float wsh[128];
    int g = blockIdx.x, b = blockIdx.y;
    int tid = threadIdx.x, lane = tid & 31, w = tid >> 5;

    qsh[tid] = g_Q[((size_t)b*Gg + g)*Hh + tid];

    int idxLast = last[b*Gg + g];
    const float2* cb = (const float2*)coords + (size_t)b*Nn;
    float2 lc = cb[idxLast];

    // each thread builds 4 packed keys (dist_bits<<32 | n); OOB/masked -> huge
    unsigned long long k0, k1, k2, k3;
    {
        const float* mrow = mask + ((size_t)b*Gg + g)*Nn;
        unsigned long long kk[4];
#pragma unroll
        for (int i = 0; i < 4; ++i) {
            int n = w*128 + lane + 32*i;
            unsigned long long key = ~0ull;
            if (n < Nn) {
                float m = mrow[n];
                if (m == -INFINITY) {
                    key = (0x7F800000ull << 32) | (unsigned)n;   // +inf distance
                } else {
                    float2 c = cb[n];
                    float dx = lc.x - c.x, dy = lc.y - c.y;
                    float d = sqrtf(dx*dx + dy*dy);
                    key = ((unsigned long long)__float_as_uint(d) << 32) | (unsigned)n;
                }
            }
            kk[i] = key;
        }
        k0 = kk[0]; k1 = kk[1]; k2 = kk[2]; k3 = kk[3];
        // sort 4 ascending (network)
        cswap(k0, k1); cswap(k2, k3); cswap(k0, k2); cswap(k1, k3); cswap(k1, k2);
    }

    // warp-local top-16: 16 butterfly-min passes over sorted heads
#pragma unroll
    for (int it = 0; it < KNB; ++it) {
        unsigned long long key = k0;
#pragma unroll
        for (int off = 16; off; off >>= 1)
            key = min(key, __shfl_xor_sync(0xffffffffu, key, off));
        if (k0 == key) { k0 = k1; k1 = k2; k2 = k3; k3 = ~0ull; }  // unique keys: one winner
        if (lane == 0) warp16[w][it] = key;
    }
    __syncthreads();

    // serial 4-way merge of sorted 16-lists -> global top-16 (exact, tie-safe)
    if (tid == 0) {
        int p0 = 0, p1 = 0, p2 = 0, p3 = 0;
#pragma unroll
        for (int it = 0; it < KNB; ++it) {
            unsigned long long c0 = warp16[0][p0], c1 = warp16[1][p1];
            unsigned long long c2 = warp16[2][p2], c3 = warp16[3][p3];
            unsigned long long m01 = min(c0, c1), m23 = min(c2, c3);
            unsigned long long m = min(m01, m23);
            sel[it] = (int)(m & 0xffffffffu);
            if (m == c0) ++p0; else if (m == c1) ++p1; else if (m == c2) ++p2; else ++p3;
        }
    }
    __syncthreads();

    // attention: thread (h,j) does the full 16-dim dot for head h, neighbor j
    int h = tid >> 4, j = tid & 15;
    {
        int n = sel[j];
        const float* Krow = g_K + ((size_t)b*Nn + n)*Hh + h*16;
        const float* Vrow = g_V + ((size_t)b*Nn + n)*Hh + h*16;
        float4 q0 = *(const float4*)(qsh + h*16);
        float4 q1 = *(const float4*)(qsh + h*16 + 4);
        float4 q2 = *(const float4*)(qsh + h*16 + 8);
        float4 q3 = *(const float4*)(qsh + h*16 + 12);
        float4 kk0 = *(const float4*)(Krow);
        float4 kk1 = *(const float4*)(Krow + 4);
        float4 kk2 = *(const float4*)(Krow + 8);
        float4 kk3 = *(const float4*)(Krow + 12);
        float p = q0.x*kk0.x + q0.y*kk0.y + q0.z*kk0.z + q0.w*kk0.w
                + q1.x*kk1.x + q1.y*kk1.y + q1.z*kk1.z + q1.w*kk1.w
                + q2.x*kk2.x + q2.y*kk2.y + q2.z*kk2.z + q2.w*kk2.w
                + q3.x*kk3.x + q3.y*kk3.y + q3.z*kk3.z + q3.w*kk3.w;
        p *= 0.25f;   // 1/sqrt(16)
        // stage V head-slice to smem
        *(float4*)(vsh + j*132 + h*16)      = *(const float4*)(Vrow);
        *(float4*)(vsh + j*132 + h*16 + 4)  = *(const float4*)(Vrow + 4);
        *(float4*)(vsh + j*132 + h*16 + 8)  = *(const float4*)(Vrow + 8);
        *(float4*)(vsh + j*132 + h*16 + 12) = *(const float4*)(Vrow + 12);
        // softmax over j (width-16 segments align with heads)
        float mx = p;
#pragma unroll
        for (int off = 8; off; off >>= 1) mx = fmaxf(mx, __shfl_xor_sync(0xffffffffu, mx, off, 16));
        float e = __expf(p - mx);
        float s = e;
#pragma unroll
        for (int off = 8; off; off >>= 1) s += __shfl_xor_sync(0xffffffffu, s, off, 16);
        wsh[tid] = e * (1.f / s);
    }
    __syncthreads();

    // output: thread (h,d) combines 16 neighbors
    float o = 0.f;
#pragma unroll
    for (int j2 = 0; j2 < KNB; ++j2) o += wsh[h*16 + j2] * vsh[j2*132 + tid];
    g_attnT[(size_t)b*Hh*Gg + tid*Gg + g] = o;
}

// ---------------- F1: pointer GEMM + tanh + mask -> scores in out ----------------
__global__ __launch_bounds__(256, 2) void final_gemm_kernel(const float* __restrict__ mask,
                                                            float* __restrict__ out) {
    extern __shared__ float sm[];
    float* As = sm;
    float* Bs = sm + 8192;
    int b = blockIdx.z, n0 = blockIdx.x * 128, g0 = blockIdx.y * 128;
    int tid = threadIdx.x;
    int ty = tid >> 4, tx = tid & 15;
    unsigned long long acc[4][8];
#pragma unroll
    for (int rp = 0; rp < 4; ++rp)
#pragma unroll
        for (int c = 0; c < 8; ++c) acc[rp][c] = 0ull;

    const float* attnTb = g_attnT + (size_t)b*Hh*Gg;
    const float* EpTb   = g_EpT   + (size_t)b*Hh*Nn;
#pragma unroll
    for (int kc = 0; kc < 2; ++kc) {
        fill_k(As, attnTb, Gg, g0, Gg, kc, tid);
        fill_k(Bs, EpTb,   Nn, n0, Nn, kc, tid);
        __syncthreads();
        mm64(As, Bs, ty, tx, acc);
        __syncthreads();
    }
    float accf[8][8];
    unpack_acc(acc, accf);

    float be[8];
#pragma unroll
    for (int q = 0; q < 8; ++q) {
        int n = n0 + tx*8 + q;
        be[q] = (n < Nn) ? g_biasE[b*Nn + n] : 0.f;
    }
#pragma unroll
    for (int p = 0; p < 8; ++p) {
        int g = g0 + ty*8 + p;
        if (g >= Gg) continue;
        const float* mrow = mask + ((size_t)b*Gg + g)*Nn;
        float* orow = out + ((size_t)b*Gg + g)*Nn;
#pragma unroll
        for (int q = 0; q < 8; ++q) {
            int n = n0 + tx*8 + q;
            if (n >= Nn) continue;
            float s = accf[p][q] + be[q];
            orow[n] = fast_tanh(s) * 10.0f + mrow[n];
        }
    }
}

// ---------------- F2: warp-per-row softmax, in place on out ----------------
__global__ __launch_bounds__(256) void softmax_kernel(float* __restrict__ out) {
    int warp = threadIdx.x >> 5, lane = threadIdx.x & 31;
    int r = blockIdx.x * 8 + warp;
    if (r >= Bsz*Gg) return;
    float* row = out + (size_t)r*Nn;
    float v[16];
    float m = -INFINITY;
#pragma unroll
    for (int i = 0; i < 16; ++i) {
        int n = lane + i*32;
        v[i] = (n < Nn) ? row[n] : -INFINITY;
        m = fmaxf(m, v[i]);
    }
    for (int off = 16; off; off >>= 1) m = fmaxf(m, __shfl_xor_sync(0xffffffffu, m, off));
    float s = 0.f;
#pragma unroll
    for (int i = 0; i < 16; ++i) { float e = __expf(v[i] - m); v[i] = e; s += e; }
    for (int off = 16; off; off >>= 1) s += __shfl_xor_sync(0xffffffffu, s, off);
    float inv = 1.f / s;
#pragma unroll
    for (int i = 0; i < 16; ++i) {
        int n = lane + i*32;
        if (n < Nn) row[n] = v[i] * inv;
    }
}

// ---------------- host ----------------
extern "C" void kernel_launch(void* const* d_in, const int* in_sizes, int n_in,
                              void* d_out, int out_size) {
    const float* coords   = (const float*)d_in[0];
    const float* emb      = (const float*)d_in[1];
    const int*   last     = (const int*)  d_in[2];
    const float* mask     = (const float*)d_in[3];
    const float* Wq_graph = (const float*)d_in[4];
    const float* Wq_first = (const float*)d_in[5];
    const float* Wq_last  = (const float*)d_in[6];
    const float* Wk       = (const float*)d_in[7];
    const float* Wv       = (const float*)d_in[8];
    const float* Wc       = (const float*)d_in[9];
    const float* bc       = (const float*)d_in[10];
    float* out = (float*)d_out;

    cudaFuncSetAttribute(gemms_kernel,      cudaFuncAttributeMaxDynamicSharedMemorySize, 66048);
    cudaFuncSetAttribute(final_gemm_kernel, cudaFuncAttributeMaxDynamicSharedMemorySize, 65536);

    prep1_kernel<<<256, 256>>>(Wk, Wv, Wc, Wq_first, Wq_last);
    prep2_kernel<<<4096, 256>>>(emb, bc, last);
    gemms_kernel<<<512, 256, 66048>>>(Wq_graph);
    glimpse_kernel<<<dim3(Gg, Bsz), 128>>>(coords, mask, last);
    final_gemm_kernel<<<dim3(4, 4, Bsz), 256, 65536>>>(mask, out);
    softmax_kernel<<<2000, 256>>>(out);
}

// round 13
// speedup vs baseline: 1.1853x; 1.1703x over previous
#include <cuda_runtime.h>
#include <math.h>
#include <stdint.h>

#define Bsz 32
#define Nn  500
#define Gg  500
#define Hh  128
#define KNB 16

// ---------------- scratch (device globals; no allocation) ----------------
__device__ float g_colsum[Bsz*Hh];
__device__ float g_Wall[Hh*384];             // [k][j]: j<128 Wk^T, <256 Wv^T, <384 Wc
__device__ float g_WqT[Hh*Hh];               // [k][o] = Wq_first[o][k]+Wq_last[o][k]
__device__ float g_embT[Bsz*Hh*Nn];          // (B,128,N)  k-major embeddings
__device__ float g_lastT[Bsz*Hh*Gg];         // (B,128,G)  k-major gathered last_emb
__device__ float g_K[(size_t)Bsz*Nn*Hh];     // (B,N,128)
__device__ float g_V[(size_t)Bsz*Nn*Hh];     // (B,N,128)
__device__ float g_EpT[Bsz*Hh*Nn];           // (B,128,N)  E' = emb@Wc, k-major
__device__ float g_biasE[Bsz*Nn];            // bc . emb[b,n]
__device__ float g_Q[(size_t)Bsz*Gg*Hh];     // (B,G,128)
__device__ float g_attnT[Bsz*Hh*Gg];         // (B,128,G)  attention out, k-major

// ---------------- f32x2 packed-FMA fabric ----------------
__device__ __forceinline__ void ffma2(unsigned long long &d, unsigned long long a, unsigned long long b) {
    asm("fma.rn.f32x2 %0, %1, %2, %0;" : "+l"(d) : "l"(a), "l"(b));
}
__device__ __forceinline__ unsigned long long bpack(float x) {
    unsigned long long r;
    asm("mov.b64 %0, {%1, %1};" : "=l"(r) : "f"(x));
    return r;
}
__device__ __forceinline__ void unpack2(unsigned long long v, float &lo, float &hi) {
    asm("mov.b64 {%0, %1}, %2;" : "=f"(lo), "=f"(hi) : "l"(v));
}

// 64-k chunk of the 8x8 micro-tile mainloop. As/Bs: [64][128].
__device__ __forceinline__ void mm64(const float* __restrict__ As, const float* __restrict__ Bs,
                                     int ty, int tx, unsigned long long acc[4][8]) {
#pragma unroll 8
    for (int k = 0; k < 64; ++k) {
        ulonglong2 aA = *(const ulonglong2*)(As + k*128 + ty*8);
        ulonglong2 aB = *(const ulonglong2*)(As + k*128 + ty*8 + 4);
        float4 b0 = *(const float4*)(Bs + k*128 + tx*8);
        float4 b1 = *(const float4*)(Bs + k*128 + tx*8 + 4);
        unsigned long long bb[8];
        bb[0]=bpack(b0.x); bb[1]=bpack(b0.y); bb[2]=bpack(b0.z); bb[3]=bpack(b0.w);
        bb[4]=bpack(b1.x); bb[5]=bpack(b1.y); bb[6]=bpack(b1.z); bb[7]=bpack(b1.w);
#pragma unroll
        for (int c = 0; c < 8; ++c) {
            ffma2(acc[0][c], aA.x, bb[c]);
            ffma2(acc[1][c], aA.y, bb[c]);
            ffma2(acc[2][c], aB.x, bb[c]);
            ffma2(acc[3][c], aB.y, bb[c]);
        }
    }
}
__device__ __forceinline__ void unpack_acc(unsigned long long acc[4][8], float accf[8][8]) {
#pragma unroll
    for (int rp = 0; rp < 4; ++rp)
#pragma unroll
        for (int c = 0; c < 8; ++c)
            unpack2(acc[rp][c], accf[2*rp][c], accf[2*rp+1][c]);
}

// fill one [64][128] k-chunk from k-major src (row pitch), cols j0.., guard jmax
__device__ __forceinline__ void fill_k(float* __restrict__ dst, const float* __restrict__ src,
                                       int pitch, int j0, int jmax, int kc, int tid) {
#pragma unroll
    for (int it = 0; it < 8; ++it) {
        int idx = tid + it*256;          // 2048 float4 slots
        int k = idx >> 5, jq = idx & 31;
        int j = j0 + jq*4;
        const float* p = src + (size_t)(kc*64 + k)*pitch + j;
        float4 v;
        if (j + 3 < jmax) v = *(const float4*)p;
        else {
            v.x = (j   < jmax) ? p[0] : 0.f;
            v.y = (j+1 < jmax) ? p[1] : 0.f;
            v.z = (j+2 < jmax) ? p[2] : 0.f;
            v.w = (j+3 < jmax) ? p[3] : 0.f;
        }
        *(float4*)(dst + k*128 + jq*4) = v;
    }
}

// fast tanh: (1 - e) * rcp(1 + e), e = exp(-2|x|); err ~1e-7
__device__ __forceinline__ float fast_tanh(float x) {
    float a = fabsf(x);
    float e = __expf(-2.f * a);
    float t = __fdividef(1.f - e, 1.f + e);
    return copysignf(t, x);
}

// ---------------- prep1: weight transposes + zero colsum/biasE ----------------
__global__ void prep1_kernel(const float* __restrict__ Wk, const float* __restrict__ Wv,
                             const float* __restrict__ Wc, const float* __restrict__ Wqf,
                             const float* __restrict__ Wql) {
    int idx = blockIdx.x * blockDim.x + threadIdx.x;
    const int total1 = Hh * 384;
    if (idx < total1) {
        int k = idx / 384, j = idx % 384;
        float v;
        if (j < 128)      v = Wk[j*128 + k];
        else if (j < 256) v = Wv[(j-128)*128 + k];
        else              v = Wc[k*128 + (j-256)];
        g_Wall[idx] = v;
    }
    int idx2 = idx - total1;
    if (idx2 >= 0 && idx2 < Hh*Hh) {
        int k = idx2 / 128, o = idx2 % 128;
        g_WqT[idx2] = Wqf[o*128 + k] + Wql[o*128 + k];
    }
    if (idx < Bsz*Hh) g_colsum[idx] = 0.f;
    if (idx < Bsz*Nn) g_biasE[idx] = 0.f;
}

// ---------------- prep2: embT(+colsum+biasE) and lastT, merged ----------------
__global__ void prep2_kernel(const float* __restrict__ emb, const float* __restrict__ bc,
                             const int* __restrict__ last) {
    __shared__ float tile[32][33];
    int tid = threadIdx.x;
    int tx = tid & 31, ty = tid >> 5;
    int bid = blockIdx.x;
    if (bid < 2048) {
        int b = bid >> 6, k0 = ((bid >> 4) & 3) * 32, n0 = (bid & 15) * 32;
        float bcv = bc[k0 + tx];
        float csum = 0.f;
#pragma unroll
        for (int i = 0; i < 32; i += 8) {
            int n = n0 + ty + i;
            float v = 0.f;
            if (n < Nn) { v = emb[((size_t)b*Nn + n)*Hh + k0 + tx]; tile[ty+i][tx] = v; }
            csum += v;
            float contrib = v * bcv;
            for (int off = 16; off; off >>= 1)
                contrib += __shfl_xor_sync(0xffffffffu, contrib, off);
            if (tx == 0 && n < Nn) atomicAdd(&g_biasE[b*Nn + n], contrib);
        }
        atomicAdd(&g_colsum[b*128 + k0 + tx], csum);
        __syncthreads();
#pragma unroll
        for (int i = 0; i < 32; i += 8) {
            int k = k0 + ty + i, n = n0 + tx;
            if (n < Nn) g_embT[(size_t)b*Hh*Nn + k*Nn + n] = tile[tx][ty+i];
        }
    } else {
        int e = bid - 2048;
        int b = e >> 6, k0 = ((e >> 4) & 3) * 32, g0 = (e & 15) * 32;
#pragma unroll
        for (int i = 0; i < 32; i += 8) {
            int g = g0 + ty + i;
            if (g < Gg) {
                int row = last[b*Gg + g];
                tile[ty+i][tx] = emb[((size_t)b*Nn + row)*Hh + k0 + tx];
            }
        }
        __syncthreads();
#pragma unroll
        for (int i = 0; i < 32; i += 8) {
            int k = k0 + ty + i, g = g0 + tx;
            if (g < Gg) g_lastT[(size_t)b*Hh*Gg + k*Gg + g] = tile[tx][ty+i];
        }
    }
}

// ---------------- gemms: A-path (K|V|E') and Q-path (+q_graph), merged ----------------
__global__ __launch_bounds__(256, 2) void gemms_kernel(const float* __restrict__ Wqg) {
    extern __shared__ float sm[];
    float* As = sm;
    float* Bs = sm + 8192;
    __shared__ float mean_s[128];
    __shared__ float qg_s[128];
    int tid = threadIdx.x;
    int bid = blockIdx.x;
    int ty = tid >> 4, tx = tid & 15;
    unsigned long long acc[4][8];
#pragma unroll
    for (int rp = 0; rp < 4; ++rp)
#pragma unroll
        for (int c = 0; c < 8; ++c) acc[rp][c] = 0ull;

    if (bid < 384) {
        int c = bid % 3, nt = (bid / 3) % 4, b = bid / 12;
        int c0 = c * 128, n0 = nt * 128;
        const float* embTb = g_embT + (size_t)b*Hh*Nn;
#pragma unroll
        for (int kc = 0; kc < 2; ++kc) {
            fill_k(As, embTb, Nn, n0, Nn, kc, tid);
            fill_k(Bs, g_Wall, 384, c0, 1 << 30, kc, tid);
            __syncthreads();
            mm64(As, Bs, ty, tx, acc);
            __syncthreads();
        }
        float accf[8][8];
        unpack_acc(acc, accf);
        if (c0 < 256) {
            float* dst = (c0 == 0) ? g_K : g_V;
#pragma unroll
            for (int p = 0; p < 8; ++p) {
                int r = n0 + ty*8 + p;
                if (r >= Nn) continue;
                float* o = dst + ((size_t)b*Nn + r)*Hh + tx*8;
                *(float4*)o       = make_float4(accf[p][0], accf[p][1], accf[p][2], accf[p][3]);
                *(float4*)(o + 4) = make_float4(accf[p][4], accf[p][5], accf[p][6], accf[p][7]);
            }
        } else {
            float* st = sm;  // [128][129]
#pragma unroll
            for (int q = 0; q < 8; ++q)
#pragma unroll
                for (int p = 0; p < 8; ++p)
                    st[(tx*8 + q)*129 + ty*8 + p] = accf[p][q];
            __syncthreads();
            float* EpTb = g_EpT + (size_t)b*Hh*Nn;
            for (int s = tid; s < 16384; s += 256) {
                int cc = s >> 7, n = s & 127;
                if (n0 + n < Nn) EpTb[(size_t)cc*Nn + n0 + n] = st[cc*129 + n];
            }
        }
    } else {
        int q = bid - 384;
        int gt = q % 4, b = q / 4;
        int g0 = gt * 128;
        if (tid < 128) mean_s[tid] = g_colsum[b*128 + tid] * (1.f / (float)Nn);
        __syncthreads();
        {
            int w = tid >> 5, lane = tid & 31;
            for (int o = w*16; o < w*16 + 16; ++o) {
                float s = 0.f;
#pragma unroll
                for (int i = lane; i < 128; i += 32) s += mean_s[i] * Wqg[o*128 + i];
                for (int off = 16; off; off >>= 1) s += __shfl_xor_sync(0xffffffffu, s, off);
                if (lane == 0) qg_s[o] = s;
            }
        }
        const float* lastTb = g_lastT + (size_t)b*Hh*Gg;
#pragma unroll
        for (int kc = 0; kc < 2; ++kc) {
            fill_k(As, lastTb, Gg, g0, Gg, kc, tid);
            fill_k(Bs, g_WqT, 128, 0, 1 << 30, kc, tid);
            __syncthreads();
            mm64(As, Bs, ty, tx, acc);
            __syncthreads();
        }
        float accf[8][8];
        unpack_acc(acc, accf);
        float4 qg0 = *(const float4*)(qg_s + tx*8);
        float4 qg1 = *(const float4*)(qg_s + tx*8 + 4);
#pragma unroll
        for (int p = 0; p < 8; ++p) {
            int r = g0 + ty*8 + p;
            if (r >= Gg) continue;
            float* o = g_Q + ((size_t)b*Gg + r)*Hh + tx*8;
            *(float4*)o       = make_float4(accf[p][0]+qg0.x, accf[p][1]+qg0.y, accf[p][2]+qg0.z, accf[p][3]+qg0.w);
            *(float4*)(o + 4) = make_float4(accf[p][4]+qg1.x, accf[p][5]+qg1.y, accf[p][6]+qg1.z, accf[p][7]+qg1.w);
        }
    }
}

// ---------------- glimpse: redux-based warp-local top-16 + R9 attention ----------------
__device__ __forceinline__ void cswap(unsigned long long &a, unsigned long long &b) {
    unsigned long long lo = min(a, b), hi = max(a, b);
    a = lo; b = hi;
}

__global__ __launch_bounds__(128) void glimpse_kernel(const float* __restrict__ coords,
                                                      const float* __restrict__ mask,
                                                      const int* __restrict__ last) {
    __shared__ unsigned long long warp16[4][16];
    __shared__ int   sel[KNB];
    __shared__ float vsh[KNB*128];
    __shared__ float ssc[128];
    __shared__ float wsh[128];
    int g = blockIdx.x, b = blockIdx.y;
    int tid = threadIdx.x, lane = tid & 31, w = tid >> 5;

    int idxLast = last[b*Gg + g];
    const float2* cb = (const float2*)coords + (size_t)b*Nn;
    float2 lc = cb[idxLast];

    // each thread builds 4 packed keys (dist_bits<<32 | n); OOB/masked -> huge
    unsigned long long k0, k1, k2, k3;
    {
        const float* mrow = mask + ((size_t)b*Gg + g)*Nn;
        unsigned long long kk[4];
#pragma unroll
        for (int i = 0; i < 4; ++i) {
            int n = w*128 + lane + 32*i;
            unsigned long long key = ~0ull;
            if (n < Nn) {
                float m = mrow[n];
                if (m == -INFINITY) {
                    key = (0x7F800000ull << 32) | (unsigned)n;   // +inf distance
                } else {
                    float2 c = cb[n];
                    float dx = lc.x - c.x, dy = lc.y - c.y;
                    float d = sqrtf(dx*dx + dy*dy);
                    key = ((unsigned long long)__float_as_uint(d) << 32) | (unsigned)n;
                }
            }
            kk[i] = key;
        }
        k0 = kk[0]; k1 = kk[1]; k2 = kk[2]; k3 = kk[3];
        // sort 4 ascending (network)
        cswap(k0, k1); cswap(k2, k3); cswap(k0, k2); cswap(k1, k3); cswap(k1, k2);
    }

    // warp-local top-16 via two u32 redux.min per round (dist, then index tie-break)
#pragma unroll
    for (int it = 0; it < KNB; ++it) {
        uint32_t hd = (uint32_t)(k0 >> 32);
        uint32_t m  = __reduce_min_sync(0xffffffffu, hd);
        uint32_t cn = (hd == m) ? (uint32_t)k0 : 0xffffffffu;
        uint32_t wn = __reduce_min_sync(0xffffffffu, cn);
        if (hd == m && (uint32_t)k0 == wn) { k0 = k1; k1 = k2; k2 = k3; k3 = ~0ull; }
        if (lane == 0) warp16[w][it] = ((unsigned long long)m << 32) | wn;
    }
    __syncthreads();

    // serial 4-way merge of sorted 16-lists -> global top-16 (exact, tie-safe)
    if (tid == 0) {
        int p0 = 0, p1 = 0, p2 = 0, p3 = 0;
#pragma unroll
        for (int it = 0; it < KNB; ++it) {
            unsigned long long c0 = warp16[0][p0], c1 = warp16[1][p1];
            unsigned long long c2 = warp16[2][p2], c3 = warp16[3][p3];
            unsigned long long m01 = min(c0, c1), m23 = min(c2, c3);
            unsigned long long m = min(m01, m23);
            sel[it] = (int)(m & 0xffffffffu);
            if (m == c0) ++p0; else if (m == c1) ++p1; else if (m == c2) ++p2; else ++p3;
        }
    }
    __syncthreads();

    // sparse attention over the 16 selected keys (R9: coalesced loads, serial j)
    float qv = g_Q[((size_t)b*Gg + g)*Hh + tid];
#pragma unroll
    for (int j = 0; j < KNB; ++j) {
        int n = sel[j];
        size_t base = ((size_t)b*Nn + n)*Hh;
        float kv = g_K[base + tid];
        vsh[j*128 + tid] = g_V[base + tid];
        float p = qv * kv;
        p += __shfl_xor_sync(0xffffffffu, p, 8, 16);
        p += __shfl_xor_sync(0xffffffffu, p, 4, 16);
        p += __shfl_xor_sync(0xffffffffu, p, 2, 16);
        p += __shfl_xor_sync(0xffffffffu, p, 1, 16);
        if ((tid & 15) == 0) ssc[(tid >> 4)*16 + j] = p * 0.25f;
    }
    __syncthreads();

    if (tid < 8) {
        float mx = -INFINITY;
#pragma unroll
        for (int j = 0; j < KNB; ++j) mx = fmaxf(mx, ssc[tid*16 + j]);
        float s = 0.f;
#pragma unroll
        for (int j = 0; j < KNB; ++j) { float e = __expf(ssc[tid*16 + j] - mx); wsh[tid*16 + j] = e; s += e; }
        float inv = 1.f / s;
#pragma unroll
        for (int j = 0; j < KNB; ++j) wsh[tid*16 + j] *= inv;
    }
    __syncthreads();

    int h = tid >> 4;
    float o = 0.f;
#pragma unroll
    for (int j = 0; j < KNB; ++j) o += wsh[h*16 + j] * vsh[j*128 + tid];
    g_attnT[(size_t)b*Hh*Gg + tid*Gg + g] = o;
}

// ---------------- F1: pointer GEMM + tanh + mask -> scores in out ----------------
__global__ __launch_bounds__(256, 2) void final_gemm_kernel(const float* __restrict__ mask,
                                                            float* __restrict__ out) {
    extern __shared__ float sm[];
    float* As = sm;
    float* Bs = sm + 8192;
    int b = blockIdx.z, n0 = blockIdx.x * 128, g0 = blockIdx.y * 128;
    int tid = threadIdx.x;
    int ty = tid >> 4, tx = tid & 15;
    unsigned long long acc[4][8];
#pragma unroll
    for (int rp = 0; rp < 4; ++rp)
#pragma unroll
        for (int c = 0; c < 8; ++c) acc[rp][c] = 0ull;

    const float* attnTb = g_attnT + (size_t)b*Hh*Gg;
    const float* EpTb   = g_EpT   + (size_t)b*Hh*Nn;
#pragma unroll
    for (int kc = 0; kc < 2; ++kc) {
        fill_k(As, attnTb, Gg, g0, Gg, kc, tid);
        fill_k(Bs, EpTb,   Nn, n0, Nn, kc, tid);
        __syncthreads();
        mm64(As, Bs, ty, tx, acc);
        __syncthreads();
    }
    float accf[8][8];
    unpack_acc(acc, accf);

    float be[8];
#pragma unroll
    for (int q = 0; q < 8; ++q) {
        int n = n0 + tx*8 + q;
        be[q] = (n < Nn) ? g_biasE[b*Nn + n] : 0.f;
    }
#pragma unroll
    for (int p = 0; p < 8; ++p) {
        int g = g0 + ty*8 + p;
        if (g >= Gg) continue;
        const float* mrow = mask + ((size_t)b*Gg + g)*Nn;
        float* orow = out + ((size_t)b*Gg + g)*Nn;
#pragma unroll
        for (int q = 0; q < 8; ++q) {
            int n = n0 + tx*8 + q;
            if (n >= Nn) continue;
            float s = accf[p][q] + be[q];
            orow[n] = fast_tanh(s) * 10.0f + mrow[n];
        }
    }
}

// ---------------- F2: warp-per-row softmax, in place on out ----------------
__global__ __launch_bounds__(256) void softmax_kernel(float* __restrict__ out) {
    int warp = threadIdx.x >> 5, lane = threadIdx.x & 31;
    int r = blockIdx.x * 8 + warp;
    if (r >= Bsz*Gg) return;
    float* row = out + (size_t)r*Nn;
    float v[16];
    float m = -INFINITY;
#pragma unroll
    for (int i = 0; i < 16; ++i) {
        int n = lane + i*32;
        v[i] = (n < Nn) ? row[n] : -INFINITY;
        m = fmaxf(m, v[i]);
    }
    for (int off = 16; off; off >>= 1) m = fmaxf(m, __shfl_xor_sync(0xffffffffu, m, off));
    float s = 0.f;
#pragma unroll
    for (int i = 0; i < 16; ++i) { float e = __expf(v[i] - m); v[i] = e; s += e; }
    for (int off = 16; off; off >>= 1) s += __shfl_xor_sync(0xffffffffu, s, off);
    float inv = 1.f / s;
#pragma unroll
    for (int i = 0; i < 16; ++i) {
        int n = lane + i*32;
        if (n < Nn) row[n] = v[i] * inv;
    }
}

// ---------------- host ----------------
extern "C" void kernel_launch(void* const* d_in, const int* in_sizes, int n_in,
                              void* d_out, int out_size) {
    const float* coords   = (const float*)d_in[0];
    const float* emb      = (const float*)d_in[1];
    const int*   last     = (const int*)  d_in[2];
    const float* mask     = (const float*)d_in[3];
    const float* Wq_graph = (const float*)d_in[4];
    const float* Wq_first = (const float*)d_in[5];
    const float* Wq_last  = (const float*)d_in[6];
    const float* Wk       = (const float*)d_in[7];
    const float* Wv       = (const float*)d_in[8];
    const float* Wc       = (const float*)d_in[9];
    const float* bc       = (const float*)d_in[10];
    float* out = (float*)d_out;

    cudaFuncSetAttribute(gemms_kernel,      cudaFuncAttributeMaxDynamicSharedMemorySize, 66048);
    cudaFuncSetAttribute(final_gemm_kernel, cudaFuncAttributeMaxDynamicSharedMemorySize, 65536);

    prep1_kernel<<<256, 256>>>(Wk, Wv, Wc, Wq_first, Wq_last);
    prep2_kernel<<<4096, 256>>>(emb, bc, last);
    gemms_kernel<<<512, 256, 66048>>>(Wq_graph);
    glimpse_kernel<<<dim3(Gg, Bsz), 128>>>(coords, mask, last);
    final_gemm_kernel<<<dim3(4, 4, Bsz), 256, 65536>>>(mask, out);
    softmax_kernel<<<2000, 256>>>(out);
}

// round 16
// speedup vs baseline: 1.3006x; 1.0973x over previous
#include <cuda_runtime.h>
#include <math.h>
#include <stdint.h>

#define Bsz 32
#define Nn  500
#define Gg  500
#define Hh  128
#define KNB 16

// ---------------- scratch (device globals; no allocation) ----------------
__device__ float g_colsum[Bsz*Hh];
__device__ float g_Wall[Hh*384];             // [k][j]: j<128 Wk^T, <256 Wv^T, <384 Wc
__device__ float g_WqT[Hh*Hh];               // [k][o] = Wq_first[o][k]+Wq_last[o][k]
__device__ float g_embT[Bsz*Hh*Nn];          // (B,128,N)  k-major embeddings
__device__ float g_lastT[Bsz*Hh*Gg];         // (B,128,G)  k-major gathered last_emb
__device__ float g_K[(size_t)Bsz*Nn*Hh];     // (B,N,128)
__device__ float g_V[(size_t)Bsz*Nn*Hh];     // (B,N,128)
__device__ float g_EpT[Bsz*Hh*Nn];           // (B,128,N)  E' = emb@Wc, k-major
__device__ float g_biasE[Bsz*Nn];            // bc . emb[b,n]
__device__ float g_Q[(size_t)Bsz*Gg*Hh];     // (B,G,128)
__device__ float g_attnT[Bsz*Hh*Gg];         // (B,128,G)  attention out, k-major

// ---------------- f32x2 packed-FMA fabric ----------------
__device__ __forceinline__ void ffma2(unsigned long long &d, unsigned long long a, unsigned long long b) {
    asm("fma.rn.f32x2 %0, %1, %2, %0;" : "+l"(d) : "l"(a), "l"(b));
}
__device__ __forceinline__ unsigned long long bpack(float x) {
    unsigned long long r;
    asm("mov.b64 %0, {%1, %1};" : "=l"(r) : "f"(x));
    return r;
}
__device__ __forceinline__ void unpack2(unsigned long long v, float &lo, float &hi) {
    asm("mov.b64 {%0, %1}, %2;" : "=f"(lo), "=f"(hi) : "l"(v));
}

// 64-k chunk of the 8x8 micro-tile mainloop. As/Bs: [64][128].
__device__ __forceinline__ void mm64(const float* __restrict__ As, const float* __restrict__ Bs,
                                     int ty, int tx, unsigned long long acc[4][8]) {
#pragma unroll 8
    for (int k = 0; k < 64; ++k) {
        ulonglong2 aA = *(const ulonglong2*)(As + k*128 + ty*8);
        ulonglong2 aB = *(const ulonglong2*)(As + k*128 + ty*8 + 4);
        float4 b0 = *(const float4*)(Bs + k*128 + tx*8);
        float4 b1 = *(const float4*)(Bs + k*128 + tx*8 + 4);
        unsigned long long bb[8];
        bb[0]=bpack(b0.x); bb[1]=bpack(b0.y); bb[2]=bpack(b0.z); bb[3]=bpack(b0.w);
        bb[4]=bpack(b1.x); bb[5]=bpack(b1.y); bb[6]=bpack(b1.z); bb[7]=bpack(b1.w);
#pragma unroll
        for (int c = 0; c < 8; ++c) {
            ffma2(acc[0][c], aA.x, bb[c]);
            ffma2(acc[1][c], aA.y, bb[c]);
            ffma2(acc[2][c], aB.x, bb[c]);
            ffma2(acc[3][c], aB.y, bb[c]);
        }
    }
}
__device__ __forceinline__ void unpack_acc(unsigned long long acc[4][8], float accf[8][8]) {
#pragma unroll
    for (int rp = 0; rp < 4; ++rp)
#pragma unroll
        for (int c = 0; c < 8; ++c)
            unpack2(acc[rp][c], accf[2*rp][c], accf[2*rp+1][c]);
}

// fill one [64][128] k-chunk from k-major src (row pitch), cols j0.., guard jmax
__device__ __forceinline__ void fill_k(float* __restrict__ dst, const float* __restrict__ src,
                                       int pitch, int j0, int jmax, int kc, int tid) {
#pragma unroll
    for (int it = 0; it < 8; ++it) {
        int idx = tid + it*256;          // 2048 float4 slots
        int k = idx >> 5, jq = idx & 31;
        int j = j0 + jq*4;
        const float* p = src + (size_t)(kc*64 + k)*pitch + j;
        float4 v;
        if (j + 3 < jmax) v = *(const float4*)p;
        else {
            v.x = (j   < jmax) ? p[0] : 0.f;
            v.y = (j+1 < jmax) ? p[1] : 0.f;
            v.z = (j+2 < jmax) ? p[2] : 0.f;
            v.w = (j+3 < jmax) ? p[3] : 0.f;
        }
        *(float4*)(dst + k*128 + jq*4) = v;
    }
}

// fast tanh: (1 - e) * rcp(1 + e), e = exp(-2|x|); err ~1e-7
__device__ __forceinline__ float fast_tanh(float x) {
    float a = fabsf(x);
    float e = __expf(-2.f * a);
    float t = __fdividef(1.f - e, 1.f + e);
    return copysignf(t, x);
}

// ---------------- prep1: weight transposes + zero colsum/biasE ----------------
__global__ void prep1_kernel(const float* __restrict__ Wk, const float* __restrict__ Wv,
                             const float* __restrict__ Wc, const float* __restrict__ Wqf,
                             const float* __restrict__ Wql) {
    int idx = blockIdx.x * blockDim.x + threadIdx.x;
    const int total1 = Hh * 384;
    if (idx < total1) {
        int k = idx / 384, j = idx % 384;
        float v;
        if (j < 128)      v = Wk[j*128 + k];
        else if (j < 256) v = Wv[(j-128)*128 + k];
        else              v = Wc[k*128 + (j-256)];
        g_Wall[idx] = v;
    }
    int idx2 = idx - total1;
    if (idx2 >= 0 && idx2 < Hh*Hh) {
        int k = idx2 / 128, o = idx2 % 128;
        g_WqT[idx2] = Wqf[o*128 + k] + Wql[o*128 + k];
    }
    if (idx < Bsz*Hh) g_colsum[idx] = 0.f;
    if (idx < Bsz*Nn) g_biasE[idx] = 0.f;
}

// ---------------- prep2: embT(+colsum+biasE) and lastT, merged ----------------
__global__ void prep2_kernel(const float* __restrict__ emb, const float* __restrict__ bc,
                             const int* __restrict__ last) {
    __shared__ float tile[32][33];
    int tid = threadIdx.x;
    int tx = tid & 31, ty = tid >> 5;
    int bid = blockIdx.x;
    if (bid < 2048) {
        int b = bid >> 6, k0 = ((bid >> 4) & 3) * 32, n0 = (bid & 15) * 32;
        float bcv = bc[k0 + tx];
        float csum = 0.f;
#pragma unroll
        for (int i = 0; i < 32; i += 8) {
            int n = n0 + ty + i;
            float v = 0.f;
            if (n < Nn) { v = emb[((size_t)b*Nn + n)*Hh + k0 + tx]; tile[ty+i][tx] = v; }
            csum += v;
            float contrib = v * bcv;
            for (int off = 16; off; off >>= 1)
                contrib += __shfl_xor_sync(0xffffffffu, contrib, off);
            if (tx == 0 && n < Nn) atomicAdd(&g_biasE[b*Nn + n], contrib);
        }
        atomicAdd(&g_colsum[b*128 + k0 + tx], csum);
        __syncthreads();
#pragma unroll
        for (int i = 0; i < 32; i += 8) {
            int k = k0 + ty + i, n = n0 + tx;
            if (n < Nn) g_embT[(size_t)b*Hh*Nn + k*Nn + n] = tile[tx][ty+i];
        }
    } else {
        int e = bid - 2048;
        int b = e >> 6, k0 = ((e >> 4) & 3) * 32, g0 = (e & 15) * 32;
#pragma unroll
        for (int i = 0; i < 32; i += 8) {
            int g = g0 + ty + i;
            if (g < Gg) {
                int row = last[b*Gg + g];
                tile[ty+i][tx] = emb[((size_t)b*Nn + row)*Hh + k0 + tx];
            }
        }
        __syncthreads();
#pragma unroll
        for (int i = 0; i < 32; i += 8) {
            int k = k0 + ty + i, g = g0 + tx;
            if (g < Gg) g_lastT[(size_t)b*Hh*Gg + k*Gg + g] = tile[tx][ty+i];
        }
    }
}

// ---------------- gemms: A-path (K|V|E') and Q-path (+q_graph), merged ----------------
__global__ __launch_bounds__(256, 2) void gemms_kernel(const float* __restrict__ Wqg) {
    extern __shared__ float sm[];
    float* As = sm;
    float* Bs = sm + 8192;
    __shared__ float mean_s[128];
    __shared__ float qg_s[128];
    int tid = threadIdx.x;
    int bid = blockIdx.x;
    int ty = tid >> 4, tx = tid & 15;
    unsigned long long acc[4][8];
#pragma unroll
    for (int rp = 0; rp < 4; ++rp)
#pragma unroll
        for (int c = 0; c < 8; ++c) acc[rp][c] = 0ull;

    if (bid < 384) {
        int c = bid % 3, nt = (bid / 3) % 4, b = bid / 12;
        int c0 = c * 128, n0 = nt * 128;
        const float* embTb = g_embT + (size_t)b*Hh*Nn;
#pragma unroll
        for (int kc = 0; kc < 2; ++kc) {
            fill_k(As, embTb, Nn, n0, Nn, kc, tid);
            fill_k(Bs, g_Wall, 384, c0, 1 << 30, kc, tid);
            __syncthreads();
            mm64(As, Bs, ty, tx, acc);
            __syncthreads();
        }
        float accf[8][8];
        unpack_acc(acc, accf);
        if (c0 < 256) {
            float* dst = (c0 == 0) ? g_K : g_V;
#pragma unroll
            for (int p = 0; p < 8; ++p) {
                int r = n0 + ty*8 + p;
                if (r >= Nn) continue;
                float* o = dst + ((size_t)b*Nn + r)*Hh + tx*8;
                *(float4*)o       = make_float4(accf[p][0], accf[p][1], accf[p][2], accf[p][3]);
                *(float4*)(o + 4) = make_float4(accf[p][4], accf[p][5], accf[p][6], accf[p][7]);
            }
        } else {
            float* st = sm;  // [128][129]
#pragma unroll
            for (int q = 0; q < 8; ++q)
#pragma unroll
                for (int p = 0; p < 8; ++p)
                    st[(tx*8 + q)*129 + ty*8 + p] = accf[p][q];
            __syncthreads();
            float* EpTb = g_EpT + (size_t)b*Hh*Nn;
            for (int s = tid; s < 16384; s += 256) {
                int cc = s >> 7, n = s & 127;
                if (n0 + n < Nn) EpTb[(size_t)cc*Nn + n0 + n] = st[cc*129 + n];
            }
        }
    } else {
        int q = bid - 384;
        int gt = q % 4, b = q / 4;
        int g0 = gt * 128;
        if (tid < 128) mean_s[tid] = g_colsum[b*128 + tid] * (1.f / (float)Nn);
        __syncthreads();
        {
            int w = tid >> 5, lane = tid & 31;
            for (int o = w*16; o < w*16 + 16; ++o) {
                float s = 0.f;
#pragma unroll
                for (int i = lane; i < 128; i += 32) s += mean_s[i] * Wqg[o*128 + i];
                for (int off = 16; off; off >>= 1) s += __shfl_xor_sync(0xffffffffu, s, off);
                if (lane == 0) qg_s[o] = s;
            }
        }
        const float* lastTb = g_lastT + (size_t)b*Hh*Gg;
#pragma unroll
        for (int kc = 0; kc < 2; ++kc) {
            fill_k(As, lastTb, Gg, g0, Gg, kc, tid);
            fill_k(Bs, g_WqT, 128, 0, 1 << 30, kc, tid);
            __syncthreads();
            mm64(As, Bs, ty, tx, acc);
            __syncthreads();
        }
        float accf[8][8];
        unpack_acc(acc, accf);
        float4 qg0 = *(const float4*)(qg_s + tx*8);
        float4 qg1 = *(const float4*)(qg_s + tx*8 + 4);
#pragma unroll
        for (int p = 0; p < 8; ++p) {
            int r = g0 + ty*8 + p;
            if (r >= Gg) continue;
            float* o = g_Q + ((size_t)b*Gg + r)*Hh + tx*8;
            *(float4*)o       = make_float4(accf[p][0]+qg0.x, accf[p][1]+qg0.y, accf[p][2]+qg0.z, accf[p][3]+qg0.w);
            *(float4*)(o + 4) = make_float4(accf[p][4]+qg1.x, accf[p][5]+qg1.y, accf[p][6]+qg1.z, accf[p][7]+qg1.w);
        }
    }
}

// ---------------- glimpse: redux top-16 + float4 4-wide attention ----------------
__device__ __forceinline__ void cswap(unsigned long long &a, unsigned long long &b) {
    unsigned long long lo = min(a, b), hi = max(a, b);
    a = lo; b = hi;
}

__global__ __launch_bounds__(128) void glimpse_kernel(const float* __restrict__ coords,
                                                      const float* __restrict__ mask,
                                                      const int* __restrict__ last) {
    __shared__ unsigned long long warp16[4][16];
    __shared__ int   sel[KNB];
    __shared__ __align__(16) float vsh[KNB*128];
    __shared__ float ssc[128];
    __shared__ float wsh[128];
    int g = blockIdx.x, b = blockIdx.y;
    int tid = threadIdx.x, lane = tid & 31, w = tid >> 5;

    int idxLast = last[b*Gg + g];
    const float2* cb = (const float2*)coords + (size_t)b*Nn;
    float2 lc = cb[idxLast];

    // each thread builds 4 packed keys (dist_bits<<32 | n); OOB/masked -> huge
    unsigned long long k0, k1, k2, k3;
    {
        const float* mrow = mask + ((size_t)b*Gg + g)*Nn;
        unsigned long long kk[4];
#pragma unroll
        for (int i = 0; i < 4; ++i) {
            int n = w*128 + lane + 32*i;
            unsigned long long key = ~0ull;
            if (n < Nn) {
                float m = mrow[n];
                if (m == -INFINITY) {
                    key = (0x7F800000ull << 32) | (unsigned)n;   // +inf distance
                } else {
                    float2 c = cb[n];
                    float dx = lc.x - c.x, dy = lc.y - c.y;
                    float d = sqrtf(dx*dx + dy*dy);
                    key = ((unsigned long long)__float_as_uint(d) << 32) | (unsigned)n;
                }
            }
            kk[i] = key;
        }
        k0 = kk[0]; k1 = kk[1]; k2 = kk[2]; k3 = kk[3];
        // sort 4 ascending (network)
        cswap(k0, k1); cswap(k2, k3); cswap(k0, k2); cswap(k1, k3); cswap(k1, k2);
    }

    // warp-local top-16 via two u32 redux.min per round (dist, then index tie-break)
#pragma unroll
    for (int it = 0; it < KNB; ++it) {
        uint32_t hd = (uint32_t)(k0 >> 32);
        uint32_t m  = __reduce_min_sync(0xffffffffu, hd);
        uint32_t cn = (hd == m) ? (uint32_t)k0 : 0xffffffffu;
        uint32_t wn = __reduce_min_sync(0xffffffffu, cn);
        if (hd == m && (uint32_t)k0 == wn) { k0 = k1; k1 = k2; k2 = k3; k3 = ~0ull; }
        if (lane == 0) warp16[w][it] = ((unsigned long long)m << 32) | wn;
    }
    __syncthreads();

    // serial 4-way merge of sorted 16-lists -> global top-16 (exact, tie-safe)
    if (tid == 0) {
        int p0 = 0, p1 = 0, p2 = 0, p3 = 0;
#pragma unroll
        for (int it = 0; it < KNB; ++it) {
            unsigned long long c0 = warp16[0][p0], c1 = warp16[1][p1];
            unsigned long long c2 = warp16[2][p2], c3 = warp16[3][p3];
            unsigned long long m01 = min(c0, c1), m23 = min(c2, c3);
            unsigned long long m = min(m01, m23);
            sel[it] = (int)(m & 0xffffffffu);
            if (m == c0) ++p0; else if (m == c1) ++p1; else if (m == c2) ++p2; else ++p3;
        }
    }
    __syncthreads();

    // attention: 4 neighbors per iteration (one per warp), float4 rows.
    // lane covers dims lane*4..lane*4+3; head = lane>>2; width-4 shuffle reduce.
    {
        float4 qf = *(const float4*)(g_Q + ((size_t)b*Gg + g)*Hh + lane*4);
#pragma unroll
        for (int it = 0; it < 4; ++it) {
            int j = it*4 + w;
            int n = sel[j];
            size_t base = ((size_t)b*Nn + n)*Hh;
            float4 kf = *(const float4*)(g_K + base + lane*4);
            float4 vf = *(const float4*)(g_V + base + lane*4);
            *(float4*)(vsh + j*128 + lane*4) = vf;
            float p = qf.x*kf.x + qf.y*kf.y + qf.z*kf.z + qf.w*kf.w;
            p += __shfl_xor_sync(0xffffffffu, p, 1, 4);
            p += __shfl_xor_sync(0xffffffffu, p, 2, 4);
            if ((lane & 3) == 0) ssc[(lane >> 2)*16 + j] = p * 0.25f;   // 1/sqrt(16)
        }
    }
    __syncthreads();

    if (tid < 8) {
        float mx = -INFINITY;
#pragma unroll
        for (int j = 0; j < KNB; ++j) mx = fmaxf(mx, ssc[tid*16 + j]);
        float s = 0.f;
#pragma unroll
        for (int j = 0; j < KNB; ++j) { float e = __expf(ssc[tid*16 + j] - mx); wsh[tid*16 + j] = e; s += e; }
        float inv = 1.f / s;
#pragma unroll
        for (int j = 0; j < KNB; ++j) wsh[tid*16 + j] *= inv;
    }
    __syncthreads();

    int h = tid >> 4;
    float o = 0.f;
#pragma unroll
    for (int j = 0; j < KNB; ++j) o += wsh[h*16 + j] * vsh[j*128 + tid];
    g_attnT[(size_t)b*Hh*Gg + tid*Gg + g] = o;
}

// ---------------- F1: pointer GEMM + tanh + mask -> scores in out ----------------
__global__ __launch_bounds__(256, 2) void final_gemm_kernel(const float* __restrict__ mask,
                                                            float* __restrict__ out) {
    extern __shared__ float sm[];
    float* As = sm;
    float* Bs = sm + 8192;
    int b = blockIdx.z, n0 = blockIdx.x * 128, g0 = blockIdx.y * 128;
    int tid = threadIdx.x;
    int ty = tid >> 4, tx = tid & 15;
    unsigned long long acc[4][8];
#pragma unroll
    for (int rp = 0; rp < 4; ++rp)
#pragma unroll
        for (int c = 0; c < 8; ++c) acc[rp][c] = 0ull;

    const float* attnTb = g_attnT + (size_t)b*Hh*Gg;
    const float* EpTb   = g_EpT   + (size_t)b*Hh*Nn;
#pragma unroll
    for (int kc = 0; kc < 2; ++kc) {
        fill_k(As, attnTb, Gg, g0, Gg, kc, tid);
        fill_k(Bs, EpTb,   Nn, n0, Nn, kc, tid);
        __syncthreads();
        mm64(As, Bs, ty, tx, acc);
        __syncthreads();
    }
    float accf[8][8];
    unpack_acc(acc, accf);

    float be[8];
#pragma unroll
    for (int q = 0; q < 8; ++q) {
        int n = n0 + tx*8 + q;
        be[q] = (n < Nn) ? g_biasE[b*Nn + n] : 0.f;
    }
#pragma unroll
    for (int p = 0; p < 8; ++p) {
        int g = g0 + ty*8 + p;
        if (g >= Gg) continue;
        const float* mrow = mask + ((size_t)b*Gg + g)*Nn;
        float* orow = out + ((size_t)b*Gg + g)*Nn;
#pragma unroll
        for (int q = 0; q < 8; ++q) {
            int n = n0 + tx*8 + q;
            if (n >= Nn) continue;
            float s = accf[p][q] + be[q];
            orow[n] = fast_tanh(s) * 10.0f + mrow[n];
        }
    }
}

// ---------------- F2: warp-per-row softmax, in place on out ----------------
__global__ __launch_bounds__(256) void softmax_kernel(float* __restrict__ out) {
    int warp = threadIdx.x >> 5, lane = threadIdx.x & 31;
    int r = blockIdx.x * 8 + warp;
    if (r >= Bsz*Gg) return;
    float* row = out + (size_t)r*Nn;
    float v[16];
    float m = -INFINITY;
#pragma unroll
    for (int i = 0; i < 16; ++i) {
        int n = lane + i*32;
        v[i] = (n < Nn) ? row[n] : -INFINITY;
        m = fmaxf(m, v[i]);
    }
    for (int off = 16; off; off >>= 1) m = fmaxf(m, __shfl_xor_sync(0xffffffffu, m, off));
    float s = 0.f;
#pragma unroll
    for (int i = 0; i < 16; ++i) { float e = __expf(v[i] - m); v[i] = e; s += e; }
    for (int off = 16; off; off >>= 1) s += __shfl_xor_sync(0xffffffffu, s, off);
    float inv = 1.f / s;
#pragma unroll
    for (int i = 0; i < 16; ++i) {
        int n = lane + i*32;
        if (n < Nn) row[n] = v[i] * inv;
    }
}

// ---------------- host ----------------
extern "C" void kernel_launch(void* const* d_in, const int* in_sizes, int n_in,
                              void* d_out, int out_size) {
    const float* coords   = (const float*)d_in[0];
    const float* emb      = (const float*)d_in[1];
    const int*   last     = (const int*)  d_in[2];
    const float* mask     = (const float*)d_in[3];
    const float* Wq_graph = (const float*)d_in[4];
    const float* Wq_first = (const float*)d_in[5];
    const float* Wq_last  = (const float*)d_in[6];
    const float* Wk       = (const float*)d_in[7];
    const float* Wv       = (const float*)d_in[8];
    const float* Wc       = (const float*)d_in[9];
    const float* bc       = (const float*)d_in[10];
    float* out = (float*)d_out;

    cudaFuncSetAttribute(gemms_kernel,      cudaFuncAttributeMaxDynamicSharedMemorySize, 66048);
    cudaFuncSetAttribute(final_gemm_kernel, cudaFuncAttributeMaxDynamicSharedMemorySize, 65536);

    prep1_kernel<<<256, 256>>>(Wk, Wv, Wc, Wq_first, Wq_last);
    prep2_kernel<<<4096, 256>>>(emb, bc, last);
    gemms_kernel<<<512, 256, 66048>>>(Wq_graph);
    glimpse_kernel<<<dim3(Gg, Bsz), 128>>>(coords, mask, last);
    final_gemm_kernel<<<dim3(4, 4, Bsz), 256, 65536>>>(mask, out);
    softmax_kernel<<<2000, 256>>>(out);
}